// round 9
// baseline (speedup 1.0000x reference)
#include <cuda_runtime.h>
#include <cuda_bf16.h>
#include <math.h>
#include <stdint.h>

// ---------------- problem constants ----------------
#define BATCH  2048
#define DDIM   32
#define HID    512
#define NSTEPS 16
#define NELEM  (BATCH * DDIM)

// ---------------- device scratch ----------------
__device__ __align__(16) float           g_theta2[2][NELEM];
__device__ __align__(16) float           g_ksum2 [2][NELEM];
__device__ __align__(16) float           g_kpart[8 * NELEM];
__device__ __align__(16) __nv_bfloat16   g_B1t_hi[1024 * 32];
__device__ __align__(16) __nv_bfloat16   g_B1t_lo[1024 * 32];
__device__ __align__(16) __nv_bfloat16   g_B1c_hi[1024 * 128];
__device__ __align__(16) __nv_bfloat16   g_B1c_lo[1024 * 128];
__device__ __align__(16) __nv_bfloat16   g_B2_hi[1024 * HID];
__device__ __align__(16) __nv_bfloat16   g_B2_lo[1024 * HID];
__device__ __align__(16) __nv_bfloat16   g_W3t_hi[DDIM * HID];
__device__ __align__(16) __nv_bfloat16   g_W3t_lo[DDIM * HID];
__device__ __align__(16) __nv_bfloat16   g_ctx_hi[BATCH * 128];
__device__ __align__(16) __nv_bfloat16   g_ctx_lo[BATCH * 128];
__device__ __align__(16) __nv_bfloat162  g_C0p[BATCH * 1024];   // {hi,lo} of ctx@W1c+b1

// ---------------- PTX helpers (compute_100-safe) ----------------
__device__ __forceinline__ uint32_t smem_u32(const void* p) {
    uint32_t a;
    asm("{ .reg .u64 t; cvta.to.shared.u64 t, %1; cvt.u32.u64 %0, t; }"
        : "=r"(a) : "l"(p));
    return a;
}
__device__ __forceinline__ void cpasync16(uint32_t saddr, const void* g) {
    asm volatile("cp.async.cg.shared.global [%0], [%1], 16;"
                 :: "r"(saddr), "l"(g) : "memory");
}
#define CP_COMMIT() asm volatile("cp.async.commit_group;" ::: "memory")
#define CP_WAIT0()  asm volatile("cp.async.wait_group 0;" ::: "memory")
#define CP_WAIT1()  asm volatile("cp.async.wait_group 1;" ::: "memory")

__device__ __forceinline__ void ldsm4(uint32_t* r, uint32_t addr) {
    asm volatile("ldmatrix.sync.aligned.m8n8.x4.shared.b16 {%0,%1,%2,%3}, [%4];"
                 : "=r"(r[0]), "=r"(r[1]), "=r"(r[2]), "=r"(r[3]) : "r"(addr));
}
__device__ __forceinline__ void mma16816(float* c, const uint32_t* a, const uint32_t* b) {
    asm volatile("mma.sync.aligned.m16n8k16.row.col.f32.bf16.bf16.f32 "
                 "{%0,%1,%2,%3}, {%4,%5,%6,%7}, {%8,%9}, {%0,%1,%2,%3};"
                 : "+f"(c[0]), "+f"(c[1]), "+f"(c[2]), "+f"(c[3])
                 : "r"(a[0]), "r"(a[1]), "r"(a[2]), "r"(a[3]),
                   "r"(b[0]), "r"(b[1]));
}
__device__ __forceinline__ void bf16split(float v, __nv_bfloat16& h, __nv_bfloat16& l) {
    h = __float2bfloat16(v);
    l = __float2bfloat16(v - __bfloat162float(h));
}
__device__ __forceinline__ float c0val(__nv_bfloat162 p) {
    return __bfloat162float(p.x) + __bfloat162float(p.y);
}

// ---------------- init kernels ----------------
__global__ void init_b1t(const float* __restrict__ W1) {
    int idx = blockIdx.x * 256 + threadIdx.x;          // 1024*32
    int n = idx >> 5, k = idx & 31;
    __nv_bfloat16 h, l; bf16split(W1[(size_t)k * 1024 + n], h, l);
    g_B1t_hi[idx] = h; g_B1t_lo[idx] = l;
}
__global__ void init_b1c(const float* __restrict__ W1) {
    int idx = blockIdx.x * 256 + threadIdx.x;          // 1024*128
    int n = idx >> 7, k = idx & 127;
    __nv_bfloat16 h, l; bf16split(W1[(size_t)(33 + k) * 1024 + n], h, l);
    g_B1c_hi[idx] = h; g_B1c_lo[idx] = l;
}
__global__ void init_b2(const float* __restrict__ W2) {
    int idx = blockIdx.x * 256 + threadIdx.x;          // 1024*512
    int n = idx >> 9, k = idx & 511;
    __nv_bfloat16 h, l; bf16split(W2[(size_t)k * 1024 + n], h, l);
    g_B2_hi[idx] = h; g_B2_lo[idx] = l;
}
__global__ void init_w3t(const float* __restrict__ W3) {
    int idx = blockIdx.x * 256 + threadIdx.x;          // 32*512
    int n = idx >> 9, k = idx & 511;
    __nv_bfloat16 h, l; bf16split(W3[(size_t)k * DDIM + n], h, l);
    g_W3t_hi[idx] = h; g_W3t_lo[idx] = l;
}
__global__ void init_ctx(const float* __restrict__ context) {
    int idx = blockIdx.x * 256 + threadIdx.x;          // 2048*128
    __nv_bfloat16 h, l; bf16split(context[idx], h, l);
    g_ctx_hi[idx] = h; g_ctx_lo[idx] = l;
}
__global__ void init_theta(const float* __restrict__ theta0) {
    int idx = blockIdx.x * 256 + threadIdx.x;          // 65536
    g_theta2[0][idx] = theta0[idx];
}

// ================= C0 build kernel (runs once) =================
// C0 = ctx @ W1[33:161] + b1 -> packed bf16 {hi,lo} pairs.
#define ROWE  72
#define TILE_B (128 * ROWE * 2)
#define OFF_AH 0
#define OFF_AL (TILE_B)
#define OFF_BH (2 * TILE_B)
#define OFF_BL (3 * TILE_B)
#define STAGE_B (4 * TILE_B)
#define C0_SMEM (3 * STAGE_B)           // 221184

__global__ __launch_bounds__(512)
void c0_build(const float* __restrict__ b1) {
    extern __shared__ char smem[];
    const uint32_t sb = smem_u32(smem);
    const int tid  = threadIdx.x;
    const int lane = tid & 31, wid = tid >> 5;
    const int wm = wid & 3, wn = wid >> 2;
    const int bm = blockIdx.y * 128, bn = blockIdx.x * 64;
    const int lda = 128, ldb = 128, nch = 2;

    float acc[2][4][4];
#pragma unroll
    for (int i = 0; i < 2; ++i)
#pragma unroll
        for (int j = 0; j < 4; ++j)
#pragma unroll
            for (int q = 0; q < 4; ++q) acc[i][j][q] = 0.0f;

    auto issue = [&](int c) {
        const int kc = c * 64;
        const uint32_t st = sb + (uint32_t)((c % 3) * STAGE_B);
#pragma unroll
        for (int p = 0; p < 2; ++p) {
            int slot = p * 512 + tid;
            int row = slot >> 3, cc = slot & 7;
            uint32_t so = (uint32_t)(row * ROWE + cc * 8) * 2;
            cpasync16(st + OFF_AH + so, g_ctx_hi + (size_t)(bm + row) * lda + kc + cc * 8);
            cpasync16(st + OFF_AL + so, g_ctx_lo + (size_t)(bm + row) * lda + kc + cc * 8);
            int brow = (row < 64) ? (bn + row) : (448 + bn + row);
            cpasync16(st + OFF_BH + so, g_B1c_hi + (size_t)brow * ldb + kc + cc * 8);
            cpasync16(st + OFF_BL + so, g_B1c_lo + (size_t)brow * ldb + kc + cc * 8);
        }
        CP_COMMIT();
    };

    const uint32_t a_off = (uint32_t)((wm * 32 + (lane & 15)) * ROWE
                                      + ((lane >> 4) << 3)) * 2;
    const uint32_t b_off = (uint32_t)((wn * 16 + ((lane >> 4) << 3) + (lane & 7)) * ROWE
                                      + (((lane >> 3) & 1) << 3)) * 2;

    issue(0); issue(1);
    for (int c = 0; c < nch; ++c) {
        if (c + 1 < nch) CP_WAIT1(); else CP_WAIT0();
        __syncthreads();
        const uint32_t st = sb + (uint32_t)((c % 3) * STAGE_B);
#pragma unroll
        for (int kk = 0; kk < 4; ++kk) {
            const uint32_t kb = (uint32_t)(kk * 16) * 2;
            uint32_t af[2][2][4];
#pragma unroll
            for (int mi = 0; mi < 2; ++mi) {
                uint32_t o = a_off + (uint32_t)(mi * 16 * ROWE) * 2 + kb;
                ldsm4(af[0][mi], st + OFF_AH + o);
                ldsm4(af[1][mi], st + OFF_AL + o);
            }
#pragma unroll
            for (int h = 0; h < 2; ++h) {
                uint32_t bh4[4], bl4[4];
                uint32_t o = b_off + (uint32_t)(h * 64 * ROWE) * 2 + kb;
                ldsm4(bh4, st + OFF_BH + o);
                ldsm4(bl4, st + OFF_BL + o);
#pragma unroll
                for (int mi = 0; mi < 2; ++mi)
#pragma unroll
                    for (int q = 0; q < 2; ++q) {
                        float* cc2 = acc[mi][h * 2 + q];
                        mma16816(cc2, af[0][mi], &bh4[q * 2]);
                        mma16816(cc2, af[0][mi], &bl4[q * 2]);
                        mma16816(cc2, af[1][mi], &bh4[q * 2]);
                    }
            }
        }
        __syncthreads();
    }

    const int r0 = bm + wm * 32 + (lane >> 2);
    const int cb = wn * 16 + (lane & 3) * 2;
#pragma unroll
    for (int mi = 0; mi < 2; ++mi)
#pragma unroll
        for (int q = 0; q < 2; ++q) {
            int gcol = bn + cb + q * 8;
            float bia0 = b1[gcol],       bia1 = b1[gcol + 1];
            float bib0 = b1[512 + gcol], bib1 = b1[512 + gcol + 1];
            const float* ca  = acc[mi][q];
            const float* cbv = acc[mi][2 + q];
            int ra = r0 + mi * 16;
            __nv_bfloat16 h, l;
#define PACKW(dst, v) do { bf16split((v), h, l); (dst) = __nv_bfloat162(h, l); } while (0)
            PACKW(g_C0p[(size_t)ra * 1024 + gcol],             ca[0] + bia0);
            PACKW(g_C0p[(size_t)ra * 1024 + gcol + 1],         ca[1] + bia1);
            PACKW(g_C0p[(size_t)ra * 1024 + 512 + gcol],       cbv[0] + bib0);
            PACKW(g_C0p[(size_t)ra * 1024 + 512 + gcol + 1],   cbv[1] + bib1);
            PACKW(g_C0p[(size_t)(ra + 8) * 1024 + gcol],           ca[2] + bia0);
            PACKW(g_C0p[(size_t)(ra + 8) * 1024 + gcol + 1],       ca[3] + bia1);
            PACKW(g_C0p[(size_t)(ra + 8) * 1024 + 512 + gcol],     cbv[2] + bib0);
            PACKW(g_C0p[(size_t)(ra + 8) * 1024 + 512 + gcol + 1], cbv[3] + bib1);
#undef PACKW
        }
}

// ================= fused eval kernel (one per vf evaluation) =================
// grid (8,16), 512 thr. Per chunk c (8 of them):
//   producer: h1 chunk = GLU(args@B1t + C0 + t*W1[32]) -> smem H1 tile
//   consumer: acc2 += h1_chunk @ B2_chunk  (3-term bf16 split)
// tail: g = GLU(acc2+b2) -> smem; kpart[bn] = g @ W3slice^T.
#define R2      40
#define A1P     (128 * R2 * 2)          // 10240
#define A1_OFF  0                       // 2*A1P = 20480
#define B1T_OFF 20480
#define B1T_P   10240
#define B1T_STG 20480                   // x3 -> 61440
#define B2_OFF  81920
#define B2_P    18432
#define B2_STG  36864                   // x3 -> 110592
#define H1_OFF  192512
#define H1_P    18432                   // hi; lo at +18432
#define EV_SMEM 229376
#define W3_HI   (B1T_OFF)               // tail alias into B1t stage0
#define W3_PREC 4608
#define W3_ROWB 144

__global__ __launch_bounds__(512)
void eval_mma(const float* __restrict__ W1, const float* __restrict__ b2,
              const float* __restrict__ b3,
              int it, float tval, float dt, int s_prev, int rd, int wr) {
    extern __shared__ char smem[];
    const uint32_t sb = smem_u32(smem);
    const int tid  = threadIdx.x;
    const int lane = tid & 31, wid = tid >> 5;
    const int wm = wid & 3, wn = wid >> 2;
    const int bm = blockIdx.y * 128, bn = blockIdx.x * 64;
    const float* w132 = W1 + (size_t)32 * 1024;

    auto issue = [&](int c) {
        const int kc = c * 64;
        const uint32_t stB2 = sb + B2_OFF + (uint32_t)((c % 3) * B2_STG);
        const uint32_t stB1 = sb + B1T_OFF + (uint32_t)((c % 3) * B1T_STG);
#pragma unroll
        for (int p = 0; p < 2; ++p) {
            int slot = p * 512 + tid;
            int row = slot >> 3, cc = slot & 7;
            uint32_t so = (uint32_t)(row * ROWE + cc * 8) * 2;
            int brow = (row < 64) ? (bn + row) : (448 + bn + row);
            cpasync16(stB2 + so,        g_B2_hi + (size_t)brow * HID + kc + cc * 8);
            cpasync16(stB2 + B2_P + so, g_B2_lo + (size_t)brow * HID + kc + cc * 8);
        }
        {
            int row = tid >> 2, cc = tid & 3;       // 128 rows x 32 k
            uint32_t so = (uint32_t)(row * R2 + cc * 8) * 2;
            int zrow = (row < 64) ? (kc + row) : (448 + kc + row);
            cpasync16(stB1 + so,         g_B1t_hi + (size_t)zrow * 32 + cc * 8);
            cpasync16(stB1 + B1T_P + so, g_B1t_lo + (size_t)zrow * 32 + cc * 8);
        }
        CP_COMMIT();
    };

    issue(0); issue(1);

    // ---- RK4 arg build -> A1 smem (and state update by bn==0) ----
    {
        int r = tid >> 2, c0 = (tid & 3) * 8;
        size_t base = (size_t)(bm + r) * DDIM + c0;
        float th[8], kv[8], ks[8], arg[8];
        *(float4*)&th[0] = *(const float4*)&g_theta2[rd][base];
        *(float4*)&th[4] = *(const float4*)&g_theta2[rd][base + 4];
        if (it > 0) {
#pragma unroll
            for (int j = 0; j < 8; ++j) kv[j] = b3[c0 + j];
#pragma unroll
            for (int b = 0; b < 8; ++b) {
                float4 v0 = *(const float4*)&g_kpart[(size_t)b * NELEM + base];
                float4 v1 = *(const float4*)&g_kpart[(size_t)b * NELEM + base + 4];
                kv[0] += v0.x; kv[1] += v0.y; kv[2] += v0.z; kv[3] += v0.w;
                kv[4] += v1.x; kv[5] += v1.y; kv[6] += v1.z; kv[7] += v1.w;
            }
            if (s_prev >= 1) {
                *(float4*)&ks[0] = *(const float4*)&g_ksum2[rd][base];
                *(float4*)&ks[4] = *(const float4*)&g_ksum2[rd][base + 4];
            }
#pragma unroll
            for (int j = 0; j < 8; ++j) {
                if (s_prev == 0 || s_prev == 1) arg[j] = th[j] + 0.5f * dt * kv[j];
                else if (s_prev == 2)           arg[j] = th[j] + dt * kv[j];
                else                            arg[j] = th[j] + (dt / 6.0f) * (ks[j] + kv[j]);
            }
            if (blockIdx.x == 0) {
                float ksw[8], thw[8];
#pragma unroll
                for (int j = 0; j < 8; ++j) {
                    if (s_prev == 0)      { ksw[j] = kv[j];                thw[j] = th[j]; }
                    else if (s_prev <= 2) { ksw[j] = ks[j] + 2.0f * kv[j]; thw[j] = th[j]; }
                    else                  { ksw[j] = ks[j] + kv[j];        thw[j] = arg[j]; }
                }
                *(float4*)&g_ksum2[wr][base]      = *(float4*)&ksw[0];
                *(float4*)&g_ksum2[wr][base + 4]  = *(float4*)&ksw[4];
                *(float4*)&g_theta2[wr][base]     = *(float4*)&thw[0];
                *(float4*)&g_theta2[wr][base + 4] = *(float4*)&thw[4];
            }
        } else {
#pragma unroll
            for (int j = 0; j < 8; ++j) arg[j] = th[j];
        }
        uint32_t ao = (uint32_t)(r * R2 + c0) * 2;
#pragma unroll
        for (int j = 0; j < 4; ++j) {
            __nv_bfloat16 h0, l0, h1, l1;
            bf16split(arg[2 * j],     h0, l0);
            bf16split(arg[2 * j + 1], h1, l1);
            *(__nv_bfloat162*)(smem + A1_OFF + ao + j * 4)       = __nv_bfloat162(h0, h1);
            *(__nv_bfloat162*)(smem + A1_OFF + A1P + ao + j * 4) = __nv_bfloat162(l0, l1);
        }
    }

    // fragment offsets
    const uint32_t a1_off = (uint32_t)((wm * 32 + (lane & 15)) * R2
                                       + ((lane >> 4) << 3)) * 2;
    const uint32_t b1_off = (uint32_t)((wn * 16 + ((lane >> 4) << 3) + (lane & 7)) * R2
                                       + (((lane >> 3) & 1) << 3)) * 2;
    const uint32_t aH_off = (uint32_t)((wm * 32 + (lane & 15)) * ROWE
                                       + ((lane >> 4) << 3)) * 2;
    const uint32_t b2_off = (uint32_t)((wn * 16 + ((lane >> 4) << 3) + (lane & 7)) * ROWE
                                       + (((lane >> 3) & 1) << 3)) * 2;
    const int cb = wn * 16 + (lane & 3) * 2;

    float acc2[2][4][4];
#pragma unroll
    for (int i = 0; i < 2; ++i)
#pragma unroll
        for (int j = 0; j < 4; ++j)
#pragma unroll
            for (int q = 0; q < 4; ++q) acc2[i][j][q] = 0.0f;

    for (int c = 0; c < 8; ++c) {
        if (c + 1 < 8) CP_WAIT1(); else CP_WAIT0();
        __syncthreads();
        if (c + 2 < 8) issue(c + 2);
        if (c == 7) {
            // W3 slice load into B1t stage0 region (free since chunk 6)
            int prec = tid >> 8, s2 = tid & 255;
            int row = s2 >> 3, cc = s2 & 7;
            uint32_t so = (uint32_t)(W3_HI + prec * W3_PREC + row * W3_ROWB + cc * 16);
            const __nv_bfloat16* g = (prec ? g_W3t_lo : g_W3t_hi)
                                     + (size_t)row * HID + bn + cc * 8;
            cpasync16(sb + so, g);
            CP_COMMIT();
        }

        // ---- producer: h1 chunk -> H1 tile ----
        const uint32_t stB1 = sb + B1T_OFF + (uint32_t)((c % 3) * B1T_STG);
#pragma unroll
        for (int mi = 0; mi < 2; ++mi) {
            float acc1[4][4];
#pragma unroll
            for (int j = 0; j < 4; ++j)
#pragma unroll
                for (int q = 0; q < 4; ++q) acc1[j][q] = 0.0f;
#pragma unroll
            for (int kk = 0; kk < 2; ++kk) {
                const uint32_t kb = (uint32_t)(kk * 16) * 2;
                uint32_t a0[4], a1[4];
                uint32_t o = a1_off + (uint32_t)(mi * 16 * R2) * 2 + kb;
                ldsm4(a0, sb + A1_OFF + o);
                ldsm4(a1, sb + A1_OFF + A1P + o);
#pragma unroll
                for (int h = 0; h < 2; ++h) {
                    uint32_t bh4[4], bl4[4];
                    uint32_t ob = b1_off + (uint32_t)(h * 64 * R2) * 2 + kb;
                    ldsm4(bh4, stB1 + ob);
                    ldsm4(bl4, stB1 + B1T_P + ob);
#pragma unroll
                    for (int q = 0; q < 2; ++q) {
                        float* cc2 = acc1[h * 2 + q];
                        mma16816(cc2, a0, &bh4[q * 2]);
                        mma16816(cc2, a0, &bl4[q * 2]);
                        mma16816(cc2, a1, &bh4[q * 2]);
                    }
                }
            }
            // epilogue for this mi
            int rl0 = wm * 32 + (lane >> 2) + mi * 16;
#pragma unroll
            for (int q = 0; q < 2; ++q) {
                int hcol = cb + q * 8;
                int za = c * 64 + hcol;
                float wa0 = tval * w132[za],       wa1 = tval * w132[za + 1];
                float wb0 = tval * w132[512 + za], wb1 = tval * w132[512 + za + 1];
                const __nv_bfloat162* c0r0 = &g_C0p[(size_t)(bm + rl0) * 1024];
                const __nv_bfloat162* c0r1 = &g_C0p[(size_t)(bm + rl0 + 8) * 1024];
                float zA00 = acc1[q][0]     + c0val(c0r0[za])       + wa0;
                float zA01 = acc1[q][1]     + c0val(c0r0[za + 1])   + wa1;
                float zB00 = acc1[2 + q][0] + c0val(c0r0[512 + za])     + wb0;
                float zB01 = acc1[2 + q][1] + c0val(c0r0[512 + za + 1]) + wb1;
                float zA10 = acc1[q][2]     + c0val(c0r1[za])       + wa0;
                float zA11 = acc1[q][3]     + c0val(c0r1[za + 1])   + wa1;
                float zB10 = acc1[2 + q][2] + c0val(c0r1[512 + za])     + wb0;
                float zB11 = acc1[2 + q][3] + c0val(c0r1[512 + za + 1]) + wb1;
                float g00 = zA00 / (1.0f + __expf(-zB00));
                float g01 = zA01 / (1.0f + __expf(-zB01));
                float g10 = zA10 / (1.0f + __expf(-zB10));
                float g11 = zA11 / (1.0f + __expf(-zB11));
                __nv_bfloat16 h0, l0, h1, l1;
                uint32_t o0 = (uint32_t)(rl0 * ROWE + hcol) * 2;
                bf16split(g00, h0, l0); bf16split(g01, h1, l1);
                *(__nv_bfloat162*)(smem + H1_OFF + o0)        = __nv_bfloat162(h0, h1);
                *(__nv_bfloat162*)(smem + H1_OFF + H1_P + o0) = __nv_bfloat162(l0, l1);
                uint32_t o1 = (uint32_t)((rl0 + 8) * ROWE + hcol) * 2;
                bf16split(g10, h0, l0); bf16split(g11, h1, l1);
                *(__nv_bfloat162*)(smem + H1_OFF + o1)        = __nv_bfloat162(h0, h1);
                *(__nv_bfloat162*)(smem + H1_OFF + H1_P + o1) = __nv_bfloat162(l0, l1);
            }
        }
        __syncthreads();

        // ---- consumer: acc2 += H1 @ B2_chunk ----
        const uint32_t stB2 = sb + B2_OFF + (uint32_t)((c % 3) * B2_STG);
#pragma unroll
        for (int kk = 0; kk < 4; ++kk) {
            const uint32_t kb = (uint32_t)(kk * 16) * 2;
            uint32_t af[2][2][4];
#pragma unroll
            for (int mi = 0; mi < 2; ++mi) {
                uint32_t o = aH_off + (uint32_t)(mi * 16 * ROWE) * 2 + kb;
                ldsm4(af[0][mi], sb + H1_OFF + o);
                ldsm4(af[1][mi], sb + H1_OFF + H1_P + o);
            }
#pragma unroll
            for (int h = 0; h < 2; ++h) {
                uint32_t bh4[4], bl4[4];
                uint32_t o = b2_off + (uint32_t)(h * 64 * ROWE) * 2 + kb;
                ldsm4(bh4, stB2 + o);
                ldsm4(bl4, stB2 + B2_P + o);
#pragma unroll
                for (int mi = 0; mi < 2; ++mi)
#pragma unroll
                    for (int q = 0; q < 2; ++q) {
                        float* cc2 = acc2[mi][h * 2 + q];
                        mma16816(cc2, af[0][mi], &bh4[q * 2]);
                        mma16816(cc2, af[0][mi], &bl4[q * 2]);
                        mma16816(cc2, af[1][mi], &bh4[q * 2]);
                    }
            }
        }
    }

    // ---- tail: g = GLU(acc2+b2) -> H1 region; kpart = g @ W3slice^T ----
    CP_WAIT0();      // W3 slice arrived
    __syncthreads(); // consumer reads of H1 done
    {
#pragma unroll
        for (int mi = 0; mi < 2; ++mi)
#pragma unroll
            for (int q = 0; q < 2; ++q) {
                int gcol = bn + cb + q * 8;
                float bia0 = b2[gcol],       bia1 = b2[gcol + 1];
                float bib0 = b2[512 + gcol], bib1 = b2[512 + gcol + 1];
                const float* ca  = acc2[mi][q];
                const float* cbv = acc2[mi][2 + q];
                float g00 = (ca[0] + bia0) / (1.0f + __expf(-(cbv[0] + bib0)));
                float g01 = (ca[1] + bia1) / (1.0f + __expf(-(cbv[1] + bib1)));
                float g10 = (ca[2] + bia0) / (1.0f + __expf(-(cbv[2] + bib0)));
                float g11 = (ca[3] + bia1) / (1.0f + __expf(-(cbv[3] + bib1)));
                int lr = wm * 32 + (lane >> 2) + mi * 16;
                int lc = cb + q * 8;
                __nv_bfloat16 h0, l0, h1, l1;
                uint32_t o0 = (uint32_t)(lr * ROWE + lc) * 2;
                bf16split(g00, h0, l0); bf16split(g01, h1, l1);
                *(__nv_bfloat162*)(smem + H1_OFF + o0)        = __nv_bfloat162(h0, h1);
                *(__nv_bfloat162*)(smem + H1_OFF + H1_P + o0) = __nv_bfloat162(l0, l1);
                uint32_t o1 = (uint32_t)((lr + 8) * ROWE + lc) * 2;
                bf16split(g10, h0, l0); bf16split(g11, h1, l1);
                *(__nv_bfloat162*)(smem + H1_OFF + o1)        = __nv_bfloat162(h0, h1);
                *(__nv_bfloat162*)(smem + H1_OFF + H1_P + o1) = __nv_bfloat162(l0, l1);
            }
        __syncthreads();

        if (wid < 8) {
            float accs[4][4];
#pragma unroll
            for (int i = 0; i < 4; ++i)
#pragma unroll
                for (int j = 0; j < 4; ++j) accs[i][j] = 0.0f;

            const uint32_t a_b = sb + H1_OFF
                + (uint32_t)((wid * 16 + (lane & 15)) * ROWE + ((lane >> 4) << 3)) * 2;
            const uint32_t w_b = sb + W3_HI
                + (uint32_t)(((lane >> 4) << 3) + (lane & 7)) * W3_ROWB
                + (uint32_t)((((lane >> 3) & 1) << 3)) * 2;
#pragma unroll
            for (int kk = 0; kk < 4; ++kk) {
                uint32_t ah[4], al[4];
                ldsm4(ah, a_b + kk * 32);
                ldsm4(al, a_b + H1_P + kk * 32);
#pragma unroll
                for (int p = 0; p < 2; ++p) {
                    uint32_t bo = w_b + (uint32_t)(p * 16 * W3_ROWB) + kk * 32;
                    uint32_t bh4[4], bl4[4];
                    ldsm4(bh4, bo);
                    ldsm4(bl4, bo + W3_PREC);
#pragma unroll
                    for (int q = 0; q < 2; ++q) {
                        float* cc2 = accs[p * 2 + q];
                        mma16816(cc2, ah, &bh4[q * 2]);
                        mma16816(cc2, ah, &bl4[q * 2]);
                        mma16816(cc2, al, &bh4[q * 2]);
                    }
                }
            }
            float* kp = g_kpart + (size_t)blockIdx.x * NELEM;
#pragma unroll
            for (int nt = 0; nt < 4; ++nt)
#pragma unroll
                for (int half = 0; half < 2; ++half) {
                    int lr = wid * 16 + (lane >> 2) + half * 8;
                    int col = nt * 8 + (lane & 3) * 2;
                    *(float2*)(kp + (size_t)(bm + lr) * DDIM + col)
                        = make_float2(accs[nt][half * 2], accs[nt][half * 2 + 1]);
                }
        }
    }
}

// ---------------- final RK4 combine ----------------
__global__ __launch_bounds__(256)
void final_update(const float* __restrict__ b3, float dt, float* __restrict__ out) {
    int idx = blockIdx.x * 256 + threadIdx.x;
    int c = idx & 31;
    float kv = b3[c];
#pragma unroll
    for (int b = 0; b < 8; ++b)
        kv += g_kpart[(size_t)b * NELEM + idx];
    out[idx] = g_theta2[1][idx] + (dt / 6.0f) * (g_ksum2[1][idx] + kv);
}

// ---------------- host launcher ----------------
extern "C" void kernel_launch(void* const* d_in, const int* in_sizes, int n_in,
                              void* d_out, int out_size) {
    const float* theta0  = (const float*)d_in[0];
    const float* context = (const float*)d_in[1];
    const float* W1      = (const float*)d_in[2];
    const float* b1      = (const float*)d_in[3];
    const float* W2      = (const float*)d_in[4];
    const float* b2      = (const float*)d_in[5];
    const float* W3      = (const float*)d_in[6];
    const float* b3      = (const float*)d_in[7];
    float* out = (float*)d_out;

    cudaFuncSetAttribute(c0_build, cudaFuncAttributeMaxDynamicSharedMemorySize, C0_SMEM);
    cudaFuncSetAttribute(eval_mma, cudaFuncAttributeMaxDynamicSharedMemorySize, EV_SMEM);

    init_b1t<<<128, 256>>>(W1);
    init_b1c<<<512, 256>>>(W1);
    init_b2<<<2048, 256>>>(W2);
    init_w3t<<<64, 256>>>(W3);
    init_ctx<<<1024, 256>>>(context);
    init_theta<<<256, 256>>>(theta0);

    const float dt = 1.0f / NSTEPS;
    dim3 ggrid(8, 16);

    c0_build<<<ggrid, 512, C0_SMEM>>>(b1);

    for (int it = 0; it < NSTEPS * 4; ++it) {
        int s = it & 3;
        float tval = (float)(it >> 2) * dt + ((s == 0) ? 0.0f : (s < 3 ? 0.5f * dt : dt));
        int s_prev = (it - 1) & 3;
        int rd = (it == 0) ? 0 : ((it - 1) & 1);
        int wr = it & 1;
        eval_mma<<<ggrid, 512, EV_SMEM>>>(W1, b2, b3, it, tval, dt, s_prev, rd, wr);
    }
    final_update<<<256, 256>>>(b3, dt, out);
}

// round 10
// speedup vs baseline: 1.5703x; 1.5703x over previous
#include <cuda_runtime.h>
#include <cuda_bf16.h>
#include <math.h>
#include <stdint.h>

// ---------------- problem constants ----------------
#define BATCH  2048
#define DDIM   32
#define HID    512
#define NSTEPS 16
#define NELEM  (BATCH * DDIM)

// ---------------- device scratch ----------------
__device__ __align__(16) __nv_bfloat16 g_h1_hi[BATCH * HID];
__device__ __align__(16) __nv_bfloat16 g_h1_lo[BATCH * HID];
__device__ __align__(16) float         g_theta2[2][NELEM];
__device__ __align__(16) float         g_ksum2 [2][NELEM];
__device__ __align__(16) float         g_kpart[8 * NELEM];
__device__ __align__(16) __nv_bfloat16 g_B1t_hi[1024 * 32];
__device__ __align__(16) __nv_bfloat16 g_B1t_lo[1024 * 32];
__device__ __align__(16) __nv_bfloat16 g_B1c_hi[1024 * 128];
__device__ __align__(16) __nv_bfloat16 g_B1c_lo[1024 * 128];
__device__ __align__(16) __nv_bfloat16 g_B2_hi[1024 * HID];
__device__ __align__(16) __nv_bfloat16 g_B2_lo[1024 * HID];
__device__ __align__(16) __nv_bfloat16 g_W3t_hi[DDIM * HID];
__device__ __align__(16) __nv_bfloat16 g_W3t_lo[DDIM * HID];
__device__ __align__(16) __nv_bfloat16 g_ctx_hi[BATCH * 128];
__device__ __align__(16) __nv_bfloat16 g_ctx_lo[BATCH * 128];
__device__ __align__(16) float         g_C0[BATCH * 1024];    // ctx@W1c + b1 (fp32)
__device__ int g_h1flag[16 * 8];                              // per (bm16, chunk)

// ---------------- PTX helpers (compute_100-safe) ----------------
__device__ __forceinline__ uint32_t smem_u32(const void* p) {
    uint32_t a;
    asm("{ .reg .u64 t; cvta.to.shared.u64 t, %1; cvt.u32.u64 %0, t; }"
        : "=r"(a) : "l"(p));
    return a;
}
__device__ __forceinline__ void cpasync16(uint32_t saddr, const void* g) {
    asm volatile("cp.async.cg.shared.global [%0], [%1], 16;"
                 :: "r"(saddr), "l"(g) : "memory");
}
#define CP_COMMIT() asm volatile("cp.async.commit_group;" ::: "memory")
#define CP_WAIT0()  asm volatile("cp.async.wait_group 0;" ::: "memory")
#define CP_WAIT1()  asm volatile("cp.async.wait_group 1;" ::: "memory")

__device__ __forceinline__ void ldsm4(uint32_t* r, uint32_t addr) {
    asm volatile("ldmatrix.sync.aligned.m8n8.x4.shared.b16 {%0,%1,%2,%3}, [%4];"
                 : "=r"(r[0]), "=r"(r[1]), "=r"(r[2]), "=r"(r[3]) : "r"(addr));
}
__device__ __forceinline__ void mma16816(float* c, const uint32_t* a, const uint32_t* b) {
    asm volatile("mma.sync.aligned.m16n8k16.row.col.f32.bf16.bf16.f32 "
                 "{%0,%1,%2,%3}, {%4,%5,%6,%7}, {%8,%9}, {%0,%1,%2,%3};"
                 : "+f"(c[0]), "+f"(c[1]), "+f"(c[2]), "+f"(c[3])
                 : "r"(a[0]), "r"(a[1]), "r"(a[2]), "r"(a[3]),
                   "r"(b[0]), "r"(b[1]));
}
__device__ __forceinline__ void bf16split(float v, __nv_bfloat16& h, __nv_bfloat16& l) {
    h = __float2bfloat16(v);
    l = __float2bfloat16(v - __bfloat162float(h));
}
__device__ __forceinline__ void flag_release(int* p, int v) {
    asm volatile("st.release.gpu.global.b32 [%0], %1;" :: "l"(p), "r"(v) : "memory");
}
__device__ __forceinline__ int flag_acquire(const int* p) {
    int v;
    asm volatile("ld.acquire.gpu.global.b32 %0, [%1];" : "=r"(v) : "l"(p) : "memory");
    return v;
}

// ---------------- init kernels ----------------
__global__ void init_b1t(const float* __restrict__ W1) {
    int idx = blockIdx.x * 256 + threadIdx.x;
    int n = idx >> 5, k = idx & 31;
    __nv_bfloat16 h, l; bf16split(W1[(size_t)k * 1024 + n], h, l);
    g_B1t_hi[idx] = h; g_B1t_lo[idx] = l;
}
__global__ void init_b1c(const float* __restrict__ W1) {
    int idx = blockIdx.x * 256 + threadIdx.x;
    int n = idx >> 7, k = idx & 127;
    __nv_bfloat16 h, l; bf16split(W1[(size_t)(33 + k) * 1024 + n], h, l);
    g_B1c_hi[idx] = h; g_B1c_lo[idx] = l;
}
__global__ void init_b2(const float* __restrict__ W2) {
    int idx = blockIdx.x * 256 + threadIdx.x;
    int n = idx >> 9, k = idx & 511;
    __nv_bfloat16 h, l; bf16split(W2[(size_t)k * 1024 + n], h, l);
    g_B2_hi[idx] = h; g_B2_lo[idx] = l;
}
__global__ void init_w3t(const float* __restrict__ W3) {
    int idx = blockIdx.x * 256 + threadIdx.x;
    int n = idx >> 9, k = idx & 511;
    __nv_bfloat16 h, l; bf16split(W3[(size_t)k * DDIM + n], h, l);
    g_W3t_hi[idx] = h; g_W3t_lo[idx] = l;
}
__global__ void init_ctx(const float* __restrict__ context) {
    int idx = blockIdx.x * 256 + threadIdx.x;
    __nv_bfloat16 h, l; bf16split(context[idx], h, l);
    g_ctx_hi[idx] = h; g_ctx_lo[idx] = l;
}
__global__ void init_theta(const float* __restrict__ theta0) {
    int idx = blockIdx.x * 256 + threadIdx.x;
    g_theta2[0][idx] = theta0[idx];
    if (blockIdx.x == 0 && threadIdx.x < 128) g_h1flag[threadIdx.x] = 0;  // reset flags
}

// ================= C0 build (once per call): C0 = ctx @ W1[33:161] + b1 =================
#define ROWE  72
#define TILE_B (128 * ROWE * 2)
#define OFF_AH 0
#define OFF_AL (TILE_B)
#define OFF_BH (2 * TILE_B)
#define OFF_BL (3 * TILE_B)
#define STAGE_B (4 * TILE_B)            // 73728
#define W3_OFF  (3 * STAGE_B)           // 221184
#define W3_ROWB (72 * 2)
#define W3_PREC (32 * W3_ROWB)          // 4608
#define GLU_SMEM (W3_OFF + 2 * W3_PREC) // 230400
#define GLO  (128 * ROWE * 2)

__global__ __launch_bounds__(512)
void c0_build(const float* __restrict__ b1) {
    extern __shared__ char smem[];
    const uint32_t sb = smem_u32(smem);
    const int tid  = threadIdx.x;
    const int lane = tid & 31, wid = tid >> 5;
    const int wm = wid & 3, wn = wid >> 2;
    const int bm = blockIdx.y * 128, bn = blockIdx.x * 64;

    float acc[2][4][4];
#pragma unroll
    for (int i = 0; i < 2; ++i)
#pragma unroll
        for (int j = 0; j < 4; ++j)
#pragma unroll
            for (int q = 0; q < 4; ++q) acc[i][j][q] = 0.0f;

    auto issue = [&](int c) {
        const int kc = c * 64;
        const uint32_t st = sb + (uint32_t)((c % 3) * STAGE_B);
#pragma unroll
        for (int p = 0; p < 2; ++p) {
            int slot = p * 512 + tid;
            int row = slot >> 3, cc = slot & 7;
            uint32_t so = (uint32_t)(row * ROWE + cc * 8) * 2;
            cpasync16(st + OFF_AH + so, g_ctx_hi + (size_t)(bm + row) * 128 + kc + cc * 8);
            cpasync16(st + OFF_AL + so, g_ctx_lo + (size_t)(bm + row) * 128 + kc + cc * 8);
            int brow = (row < 64) ? (bn + row) : (448 + bn + row);
            cpasync16(st + OFF_BH + so, g_B1c_hi + (size_t)brow * 128 + kc + cc * 8);
            cpasync16(st + OFF_BL + so, g_B1c_lo + (size_t)brow * 128 + kc + cc * 8);
        }
        CP_COMMIT();
    };

    const uint32_t a_off = (uint32_t)((wm * 32 + (lane & 15)) * ROWE
                                      + ((lane >> 4) << 3)) * 2;
    const uint32_t b_off = (uint32_t)((wn * 16 + ((lane >> 4) << 3) + (lane & 7)) * ROWE
                                      + (((lane >> 3) & 1) << 3)) * 2;

    issue(0); issue(1);
    for (int c = 0; c < 2; ++c) {
        if (c == 0) CP_WAIT1(); else CP_WAIT0();
        __syncthreads();
        const uint32_t st = sb + (uint32_t)((c % 3) * STAGE_B);
#pragma unroll
        for (int kk = 0; kk < 4; ++kk) {
            const uint32_t kb = (uint32_t)(kk * 16) * 2;
            uint32_t af[2][2][4];
#pragma unroll
            for (int mi = 0; mi < 2; ++mi) {
                uint32_t o = a_off + (uint32_t)(mi * 16 * ROWE) * 2 + kb;
                ldsm4(af[0][mi], st + OFF_AH + o);
                ldsm4(af[1][mi], st + OFF_AL + o);
            }
#pragma unroll
            for (int h = 0; h < 2; ++h) {
                uint32_t bh4[4], bl4[4];
                uint32_t o = b_off + (uint32_t)(h * 64 * ROWE) * 2 + kb;
                ldsm4(bh4, st + OFF_BH + o);
                ldsm4(bl4, st + OFF_BL + o);
#pragma unroll
                for (int mi = 0; mi < 2; ++mi)
#pragma unroll
                    for (int q = 0; q < 2; ++q) {
                        float* cc2 = acc[mi][h * 2 + q];
                        mma16816(cc2, af[0][mi], &bh4[q * 2]);
                        mma16816(cc2, af[0][mi], &bl4[q * 2]);
                        mma16816(cc2, af[1][mi], &bh4[q * 2]);
                    }
            }
        }
        __syncthreads();
    }

    const int r0 = bm + wm * 32 + (lane >> 2);
    const int cb = wn * 16 + (lane & 3) * 2;
#pragma unroll
    for (int mi = 0; mi < 2; ++mi)
#pragma unroll
        for (int q = 0; q < 2; ++q) {
            int gcol = bn + cb + q * 8;
            float bia0 = b1[gcol],       bia1 = b1[gcol + 1];
            float bib0 = b1[512 + gcol], bib1 = b1[512 + gcol + 1];
            const float* ca  = acc[mi][q];
            const float* cbv = acc[mi][2 + q];
            int ra = r0 + mi * 16;
            *(float2*)(g_C0 + (size_t)ra * 1024 + gcol)
                = make_float2(ca[0] + bia0, ca[1] + bia1);
            *(float2*)(g_C0 + (size_t)ra * 1024 + 512 + gcol)
                = make_float2(cbv[0] + bib0, cbv[1] + bib1);
            *(float2*)(g_C0 + (size_t)(ra + 8) * 1024 + gcol)
                = make_float2(ca[2] + bia0, ca[3] + bia1);
            *(float2*)(g_C0 + (size_t)(ra + 8) * 1024 + 512 + gcol)
                = make_float2(cbv[2] + bib0, cbv[3] + bib1);
        }
}

// ================= fused producer/consumer eval kernel =================
// grid 256 (1-D): blocks 0..127 = layer-1 producers (glu1t body),
//                 blocks 128..255 = layer-2 consumers (glu2 + k3 partial body),
// synchronized per (bm16, chunk) via release/acquire flags (value it+1).
#define R2 40
#define A1P (128 * R2 * 2)               // 10240
#define B1T_OFF (2 * A1P)                // 20480

__global__ __launch_bounds__(512)
void eval_pc(const float* __restrict__ W1, const float* __restrict__ b2,
             const float* __restrict__ b3,
             int it, float tval, float dt, int s_prev, int rd, int wr) {
    extern __shared__ char smem[];
    const uint32_t sb = smem_u32(smem);
    const int tid  = threadIdx.x;
    const int lane = tid & 31, wid = tid >> 5;
    const int wm = wid & 3, wn = wid >> 2;
    const int blk = blockIdx.x;
    const int target = it + 1;

    if (blk < 128) {
        // ================= PRODUCER: layer-1 (K=32) + inline RK4 =================
        const int bnI = blk & 7, bm16 = blk >> 3;
        const int bn = bnI * 64, bm = bm16 * 128;
        const float* w132 = W1 + (size_t)32 * 1024;

        // B1t loads (128 out-rows x 32 k, hi+lo)
#pragma unroll
        for (int p = 0; p < 2; ++p) {
            int slot = p * 512 + tid;
            int prec = slot >> 9;
            int s2 = slot & 511;
            int row = s2 >> 2, cc = s2 & 3;
            uint32_t so = (uint32_t)(B1T_OFF + prec * A1P + (row * R2 + cc * 8) * 2);
            int brow = (row < 64) ? (bn + row) : (448 + bn + row);
            const __nv_bfloat16* g = (prec ? g_B1t_lo : g_B1t_hi) + (size_t)brow * 32 + cc * 8;
            cpasync16(sb + so, g);
        }
        CP_COMMIT();

        // RK4 arg build -> A1 smem (+ state update by bnI==0)
        {
            int r = tid >> 2, c0 = (tid & 3) * 8;
            size_t base = (size_t)(bm + r) * DDIM + c0;
            float th[8], kv[8], ks[8], arg[8];
            *(float4*)&th[0] = *(const float4*)&g_theta2[rd][base];
            *(float4*)&th[4] = *(const float4*)&g_theta2[rd][base + 4];
            if (it > 0) {
#pragma unroll
                for (int j = 0; j < 8; ++j) kv[j] = b3[c0 + j];
#pragma unroll
                for (int b = 0; b < 8; ++b) {
                    float4 v0 = *(const float4*)&g_kpart[(size_t)b * NELEM + base];
                    float4 v1 = *(const float4*)&g_kpart[(size_t)b * NELEM + base + 4];
                    kv[0] += v0.x; kv[1] += v0.y; kv[2] += v0.z; kv[3] += v0.w;
                    kv[4] += v1.x; kv[5] += v1.y; kv[6] += v1.z; kv[7] += v1.w;
                }
                if (s_prev >= 1) {
                    *(float4*)&ks[0] = *(const float4*)&g_ksum2[rd][base];
                    *(float4*)&ks[4] = *(const float4*)&g_ksum2[rd][base + 4];
                }
#pragma unroll
                for (int j = 0; j < 8; ++j) {
                    if (s_prev == 0 || s_prev == 1) arg[j] = th[j] + 0.5f * dt * kv[j];
                    else if (s_prev == 2)           arg[j] = th[j] + dt * kv[j];
                    else                            arg[j] = th[j] + (dt / 6.0f) * (ks[j] + kv[j]);
                }
                if (bnI == 0) {
                    float ksw[8], thw[8];
#pragma unroll
                    for (int j = 0; j < 8; ++j) {
                        if (s_prev == 0)      { ksw[j] = kv[j];                thw[j] = th[j]; }
                        else if (s_prev <= 2) { ksw[j] = ks[j] + 2.0f * kv[j]; thw[j] = th[j]; }
                        else                  { ksw[j] = ks[j] + kv[j];        thw[j] = arg[j]; }
                    }
                    *(float4*)&g_ksum2[wr][base]      = *(float4*)&ksw[0];
                    *(float4*)&g_ksum2[wr][base + 4]  = *(float4*)&ksw[4];
                    *(float4*)&g_theta2[wr][base]     = *(float4*)&thw[0];
                    *(float4*)&g_theta2[wr][base + 4] = *(float4*)&thw[4];
                }
            } else {
#pragma unroll
                for (int j = 0; j < 8; ++j) arg[j] = th[j];
            }
            uint32_t ao = (uint32_t)(r * R2 + c0) * 2;
#pragma unroll
            for (int j = 0; j < 4; ++j) {
                __nv_bfloat16 h0, l0, h1, l1;
                bf16split(arg[2 * j],     h0, l0);
                bf16split(arg[2 * j + 1], h1, l1);
                *(__nv_bfloat162*)(smem + ao + j * 4)       = __nv_bfloat162(h0, h1);
                *(__nv_bfloat162*)(smem + A1P + ao + j * 4) = __nv_bfloat162(l0, l1);
            }
        }
        CP_WAIT0();
        __syncthreads();

        // K=32 mainloop
        float acc[2][4][4];
#pragma unroll
        for (int i = 0; i < 2; ++i)
#pragma unroll
            for (int j = 0; j < 4; ++j)
#pragma unroll
                for (int q = 0; q < 4; ++q) acc[i][j][q] = 0.0f;

        const uint32_t a_off = (uint32_t)((wm * 32 + (lane & 15)) * R2
                                          + ((lane >> 4) << 3)) * 2;
        const uint32_t b_off = (uint32_t)((wn * 16 + ((lane >> 4) << 3) + (lane & 7)) * R2
                                          + (((lane >> 3) & 1) << 3)) * 2;
#pragma unroll
        for (int kk = 0; kk < 2; ++kk) {
            const uint32_t kb = (uint32_t)(kk * 16) * 2;
            uint32_t af[2][2][4];
#pragma unroll
            for (int mi = 0; mi < 2; ++mi) {
                uint32_t o = a_off + (uint32_t)(mi * 16 * R2) * 2 + kb;
                ldsm4(af[0][mi], sb + o);
                ldsm4(af[1][mi], sb + A1P + o);
            }
#pragma unroll
            for (int h = 0; h < 2; ++h) {
                uint32_t bh4[4], bl4[4];
                uint32_t o = b_off + (uint32_t)(h * 64 * R2) * 2 + kb;
                ldsm4(bh4, sb + B1T_OFF + o);
                ldsm4(bl4, sb + B1T_OFF + A1P + o);
#pragma unroll
                for (int mi = 0; mi < 2; ++mi)
#pragma unroll
                    for (int q = 0; q < 2; ++q) {
                        float* cc2 = acc[mi][h * 2 + q];
                        mma16816(cc2, af[0][mi], &bh4[q * 2]);
                        mma16816(cc2, af[0][mi], &bl4[q * 2]);
                        mma16816(cc2, af[1][mi], &bh4[q * 2]);
                    }
            }
        }

        // epilogue: + C0 + t*W1[32], GLU, write h1 hi/lo
        const int r0 = bm + wm * 32 + (lane >> 2);
        const int cb = wn * 16 + (lane & 3) * 2;
#pragma unroll
        for (int mi = 0; mi < 2; ++mi)
#pragma unroll
            for (int q = 0; q < 2; ++q) {
                int gcol = bn + cb + q * 8;
                int ra = r0 + mi * 16;
                float wa0 = tval * w132[gcol],       wa1 = tval * w132[gcol + 1];
                float wb0 = tval * w132[512 + gcol], wb1 = tval * w132[512 + gcol + 1];
                float2 c0a0 = *(const float2*)&g_C0[(size_t)ra * 1024 + gcol];
                float2 c0b0 = *(const float2*)&g_C0[(size_t)ra * 1024 + 512 + gcol];
                float2 c0a1 = *(const float2*)&g_C0[(size_t)(ra + 8) * 1024 + gcol];
                float2 c0b1 = *(const float2*)&g_C0[(size_t)(ra + 8) * 1024 + 512 + gcol];
                const float* ca  = acc[mi][q];
                const float* cbv = acc[mi][2 + q];
                float g00 = (ca[0] + c0a0.x + wa0) / (1.0f + __expf(-(cbv[0] + c0b0.x + wb0)));
                float g01 = (ca[1] + c0a0.y + wa1) / (1.0f + __expf(-(cbv[1] + c0b0.y + wb1)));
                float g10 = (ca[2] + c0a1.x + wa0) / (1.0f + __expf(-(cbv[2] + c0b1.x + wb0)));
                float g11 = (ca[3] + c0a1.y + wa1) / (1.0f + __expf(-(cbv[3] + c0b1.y + wb1)));
                size_t o0 = (size_t)ra * HID + gcol;
                size_t o1 = (size_t)(ra + 8) * HID + gcol;
                __nv_bfloat16 h0, l0, h1, l1;
                bf16split(g00, h0, l0); bf16split(g01, h1, l1);
                *(__nv_bfloat162*)(g_h1_hi + o0) = __nv_bfloat162(h0, h1);
                *(__nv_bfloat162*)(g_h1_lo + o0) = __nv_bfloat162(l0, l1);
                bf16split(g10, h0, l0); bf16split(g11, h1, l1);
                *(__nv_bfloat162*)(g_h1_hi + o1) = __nv_bfloat162(h0, h1);
                *(__nv_bfloat162*)(g_h1_lo + o1) = __nv_bfloat162(l0, l1);
            }

        // publish h1 block (bm16, chunk=bnI)
        __threadfence();
        __syncthreads();
        if (tid == 0) flag_release(&g_h1flag[bm16 * 8 + bnI], target);
        return;
    }

    // ================= CONSUMER: layer-2 GLU + k3 partial =================
    const int cblk = blk - 128;
    const int bnI = cblk & 7, bm16 = cblk >> 3;
    const int bn = bnI * 64, bm = bm16 * 128;

    float acc[2][4][4];
#pragma unroll
    for (int i = 0; i < 2; ++i)
#pragma unroll
        for (int j = 0; j < 4; ++j)
#pragma unroll
            for (int q = 0; q < 4; ++q) acc[i][j][q] = 0.0f;

    auto issue = [&](int c) {
        const int kc = c * 64;
        const uint32_t st = sb + (uint32_t)((c % 3) * STAGE_B);
        // B2 part first (flag-independent; in flight while we poll)
#pragma unroll
        for (int p = 0; p < 2; ++p) {
            int slot = p * 512 + tid;
            int row = slot >> 3, cc = slot & 7;
            uint32_t so = (uint32_t)(row * ROWE + cc * 8) * 2;
            int brow = (row < 64) ? (bn + row) : (448 + bn + row);
            cpasync16(st + OFF_BH + so, g_B2_hi + (size_t)brow * HID + kc + cc * 8);
            cpasync16(st + OFF_BL + so, g_B2_lo + (size_t)brow * HID + kc + cc * 8);
        }
        if (c == 0) {
            // W3 slice load (flag-independent)
            int prec = tid >> 8, s2 = tid & 255;
            int row = s2 >> 3, cc = s2 & 7;
            uint32_t so = (uint32_t)(W3_OFF + prec * W3_PREC + row * W3_ROWB + cc * 16);
            const __nv_bfloat16* g = (prec ? g_W3t_lo : g_W3t_hi)
                                     + (size_t)row * HID + bn + cc * 8;
            cpasync16(sb + so, g);
        }
        // wait for producer of h1 chunk c (rows bm..bm+127, cols c*64..)
        {
            const int* fp = &g_h1flag[bm16 * 8 + c];
            while (flag_acquire(fp) < target) __nanosleep(40);
        }
        // A (h1) part
#pragma unroll
        for (int p = 0; p < 2; ++p) {
            int slot = p * 512 + tid;
            int row = slot >> 3, cc = slot & 7;
            uint32_t so = (uint32_t)(row * ROWE + cc * 8) * 2;
            cpasync16(st + OFF_AH + so, g_h1_hi + (size_t)(bm + row) * HID + kc + cc * 8);
            cpasync16(st + OFF_AL + so, g_h1_lo + (size_t)(bm + row) * HID + kc + cc * 8);
        }
        CP_COMMIT();
    };

    const uint32_t a_off = (uint32_t)((wm * 32 + (lane & 15)) * ROWE
                                      + ((lane >> 4) << 3)) * 2;
    const uint32_t b_off = (uint32_t)((wn * 16 + ((lane >> 4) << 3) + (lane & 7)) * ROWE
                                      + (((lane >> 3) & 1) << 3)) * 2;
    const int cb = wn * 16 + (lane & 3) * 2;

    issue(0); issue(1);

    for (int c = 0; c < 8; ++c) {
        if (c + 1 < 8) CP_WAIT1(); else CP_WAIT0();
        __syncthreads();
        if (c + 2 < 8) issue(c + 2);

        const uint32_t st = sb + (uint32_t)((c % 3) * STAGE_B);
#pragma unroll
        for (int kk = 0; kk < 4; ++kk) {
            const uint32_t kb = (uint32_t)(kk * 16) * 2;
            uint32_t af[2][2][4];
#pragma unroll
            for (int mi = 0; mi < 2; ++mi) {
                uint32_t o = a_off + (uint32_t)(mi * 16 * ROWE) * 2 + kb;
                ldsm4(af[0][mi], st + OFF_AH + o);
                ldsm4(af[1][mi], st + OFF_AL + o);
            }
#pragma unroll
            for (int h = 0; h < 2; ++h) {
                uint32_t bh4[4], bl4[4];
                uint32_t o = b_off + (uint32_t)(h * 64 * ROWE) * 2 + kb;
                ldsm4(bh4, st + OFF_BH + o);
                ldsm4(bl4, st + OFF_BL + o);
#pragma unroll
                for (int mi = 0; mi < 2; ++mi)
#pragma unroll
                    for (int q = 0; q < 2; ++q) {
                        float* cc2 = acc[mi][h * 2 + q];
                        mma16816(cc2, af[0][mi], &bh4[q * 2]);
                        mma16816(cc2, af[0][mi], &bl4[q * 2]);
                        mma16816(cc2, af[1][mi], &bh4[q * 2]);
                    }
            }
        }
    }

    // tail: g = GLU(acc+b2) -> smem stage0; kpart = g @ W3slice^T
    __syncthreads();
    {
#pragma unroll
        for (int mi = 0; mi < 2; ++mi)
#pragma unroll
            for (int q = 0; q < 2; ++q) {
                int gcol = bn + cb + q * 8;
                float bia0 = b2[gcol],       bia1 = b2[gcol + 1];
                float bib0 = b2[512 + gcol], bib1 = b2[512 + gcol + 1];
                const float* ca  = acc[mi][q];
                const float* cbv = acc[mi][2 + q];
                float g00 = (ca[0] + bia0) / (1.0f + __expf(-(cbv[0] + bib0)));
                float g01 = (ca[1] + bia1) / (1.0f + __expf(-(cbv[1] + bib1)));
                float g10 = (ca[2] + bia0) / (1.0f + __expf(-(cbv[2] + bib0)));
                float g11 = (ca[3] + bia1) / (1.0f + __expf(-(cbv[3] + bib1)));
                int lr = wm * 32 + (lane >> 2) + mi * 16;
                int lc = cb + q * 8;
                __nv_bfloat16 h0, l0, h1, l1;
                uint32_t o0 = (uint32_t)(lr * ROWE + lc) * 2;
                bf16split(g00, h0, l0); bf16split(g01, h1, l1);
                *(__nv_bfloat162*)(smem + o0)       = __nv_bfloat162(h0, h1);
                *(__nv_bfloat162*)(smem + GLO + o0) = __nv_bfloat162(l0, l1);
                uint32_t o1 = (uint32_t)((lr + 8) * ROWE + lc) * 2;
                bf16split(g10, h0, l0); bf16split(g11, h1, l1);
                *(__nv_bfloat162*)(smem + o1)       = __nv_bfloat162(h0, h1);
                *(__nv_bfloat162*)(smem + GLO + o1) = __nv_bfloat162(l0, l1);
            }
        __syncthreads();

        if (wid < 8) {
            float accs[4][4];
#pragma unroll
            for (int i = 0; i < 4; ++i)
#pragma unroll
                for (int j = 0; j < 4; ++j) accs[i][j] = 0.0f;

            const uint32_t a_b = sb + (uint32_t)((wid * 16 + (lane & 15)) * ROWE
                                                 + ((lane >> 4) << 3)) * 2;
            const uint32_t w_b = sb + W3_OFF
                + (uint32_t)(((lane >> 4) << 3) + (lane & 7)) * W3_ROWB
                + (uint32_t)((((lane >> 3) & 1) << 3)) * 2;
#pragma unroll
            for (int kk = 0; kk < 4; ++kk) {
                uint32_t ah[4], al[4];
                ldsm4(ah, a_b + kk * 32);
                ldsm4(al, a_b + GLO + kk * 32);
#pragma unroll
                for (int p = 0; p < 2; ++p) {
                    uint32_t bo = w_b + (uint32_t)(p * 16 * W3_ROWB) + kk * 32;
                    uint32_t bh4[4], bl4[4];
                    ldsm4(bh4, bo);
                    ldsm4(bl4, bo + W3_PREC);
#pragma unroll
                    for (int q = 0; q < 2; ++q) {
                        float* cc2 = accs[p * 2 + q];
                        mma16816(cc2, ah, &bh4[q * 2]);
                        mma16816(cc2, ah, &bl4[q * 2]);
                        mma16816(cc2, al, &bh4[q * 2]);
                    }
                }
            }
            float* kp = g_kpart + (size_t)bnI * NELEM;
#pragma unroll
            for (int nt = 0; nt < 4; ++nt)
#pragma unroll
                for (int half = 0; half < 2; ++half) {
                    int lr = wid * 16 + (lane >> 2) + half * 8;
                    int col = nt * 8 + (lane & 3) * 2;
                    *(float2*)(kp + (size_t)(bm + lr) * DDIM + col)
                        = make_float2(accs[nt][half * 2], accs[nt][half * 2 + 1]);
                }
        }
    }
}

// ---------------- final RK4 combine ----------------
__global__ __launch_bounds__(256)
void final_update(const float* __restrict__ b3, float dt, float* __restrict__ out) {
    int idx = blockIdx.x * 256 + threadIdx.x;
    int c = idx & 31;
    float kv = b3[c];
#pragma unroll
    for (int b = 0; b < 8; ++b)
        kv += g_kpart[(size_t)b * NELEM + idx];
    out[idx] = g_theta2[1][idx] + (dt / 6.0f) * (g_ksum2[1][idx] + kv);
}

// ---------------- host launcher ----------------
extern "C" void kernel_launch(void* const* d_in, const int* in_sizes, int n_in,
                              void* d_out, int out_size) {
    const float* theta0  = (const float*)d_in[0];
    const float* context = (const float*)d_in[1];
    const float* W1      = (const float*)d_in[2];
    const float* b1      = (const float*)d_in[3];
    const float* W2      = (const float*)d_in[4];
    const float* b2      = (const float*)d_in[5];
    const float* W3      = (const float*)d_in[6];
    const float* b3      = (const float*)d_in[7];
    float* out = (float*)d_out;

    cudaFuncSetAttribute(c0_build, cudaFuncAttributeMaxDynamicSharedMemorySize, GLU_SMEM);
    cudaFuncSetAttribute(eval_pc,  cudaFuncAttributeMaxDynamicSharedMemorySize, GLU_SMEM);

    init_b1t<<<128, 256>>>(W1);
    init_b1c<<<512, 256>>>(W1);
    init_b2<<<2048, 256>>>(W2);
    init_w3t<<<64, 256>>>(W3);
    init_ctx<<<1024, 256>>>(context);
    init_theta<<<256, 256>>>(theta0);

    const float dt = 1.0f / NSTEPS;
    dim3 cgrid(8, 16);
    c0_build<<<cgrid, 512, GLU_SMEM>>>(b1);

    for (int it = 0; it < NSTEPS * 4; ++it) {
        int s = it & 3;
        float tval = (float)(it >> 2) * dt + ((s == 0) ? 0.0f : (s < 3 ? 0.5f * dt : dt));
        int s_prev = (it - 1) & 3;
        int rd = (it == 0) ? 0 : ((it - 1) & 1);
        int wr = it & 1;
        eval_pc<<<256, 512, GLU_SMEM>>>(W1, b2, b3, it, tval, dt, s_prev, rd, wr);
    }
    final_update<<<256, 256>>>(b3, dt, out);
}